// round 15
// baseline (speedup 1.0000x reference)
#include <cuda_runtime.h>
#include <cuda_bf16.h>
#include <cuda_fp16.h>
#include <cstdint>

// ============================================================================
// SimpleBNN on GB300 — sm_103. Round 15.
// MEASURED: bf16/f16 mma.sync m16n8k16 = real tensor HW; round-14 config:
// 512us/layer @ tensor 88.5%, occ 12.4% (2 warps/SMSP) — latency-exposed.
//   L1 (bf16): sign(x) @ sign(w1)^T + b1 -> sign -> bf16 A-tiles
//   L2 (bf16): a1 @ sign(w2)^T + b2      -> sign -> fp16 A-tiles
//   L3 (fp16): a2 @ fp16(w3)^T + b3 -> float out   [K=4096]
// Round 15: 2 CTAs/SM — CTA tile 128x128 (warp 64x32, acc 64 regs),
// stage K=64 (A16KB+B16KB), 2 slots, launch_bounds(256,2) -> 4 warps/SMSP.
// ============================================================================

#define DINL __device__ __forceinline__

// ---------------- device scratch ----------------
// A-tiles: 16KB blocks (mt*64+ks) of 128 rows x 128B (64 elems), chunk c at
//   c ^ (row&7). B-tiles: 32KB blocks (ntB*64+ks) of 256 rows x 128B.
__device__ __align__(128) uint8_t g_Ax [(size_t)64 * 64 * 16384];  // sign(x)  bf16 64MB
__device__ __align__(128) uint8_t g_W1t[(size_t)16 * 64 * 32768];  // sign(w1) bf16 32MB
__device__ __align__(128) uint8_t g_W2t[(size_t)16 * 64 * 32768];  // sign(w2) bf16 32MB
__device__ __align__(128) uint8_t g_T1 [(size_t)64 * 64 * 16384];  // a1       bf16 64MB
__device__ __align__(128) uint8_t g_T2 [(size_t)64 * 64 * 16384];  // a2       fp16 64MB
__device__ __align__(128) uint8_t g_B3 [(size_t)4 * 64 * 32768];   // w3       fp16  8MB

// ---------------- helpers ----------------
DINL uint32_t smem_u32(const void* p) {
    uint32_t a;
    asm("{ .reg .u64 t; cvta.to.shared.u64 t, %1; cvt.u32.u64 %0, t; }" : "=r"(a) : "l"(p));
    return a;
}
DINL uint32_t bf16sgn(float v) {    // sign -> bf16 bits (+-1.0 or 0)
    uint32_t u = __float_as_uint(v);
    return ((u << 1) == 0u) ? 0u : (0x3F80u | ((u >> 31) << 15));
}
DINL uint32_t fp16sgn(float v) {    // sign -> fp16 bits (+-1.0 or 0)
    uint32_t u = __float_as_uint(v);
    return ((u << 1) == 0u) ? 0u : (0x3C00u | ((u >> 31) << 15));
}

#define MBAR_INIT(addr, cnt) \
    asm volatile("mbarrier.init.shared.b64 [%0], %1;" :: "r"(addr), "r"(cnt) : "memory")
#define MBAR_EXPECT_TX(addr, tx) \
    asm volatile("mbarrier.arrive.expect_tx.shared.b64 _, [%0], %1;" \
                 :: "r"(addr), "r"(tx) : "memory")
#define MBAR_WAIT(addr, parity) do {                                          \
    asm volatile("{\n\t.reg .pred P1;\n\t"                                    \
        "WAIT_%=:\n\t"                                                        \
        "mbarrier.try_wait.parity.acquire.cta.shared::cta.b64 P1, [%0], %1, 0x989680;\n\t" \
        "@P1 bra.uni DONE_%=;\n\t"                                            \
        "bra.uni WAIT_%=;\n\t"                                                \
        "DONE_%=:\n\t}"                                                       \
        :: "r"((uint32_t)(addr)), "r"((uint32_t)(parity)) : "memory");        \
} while (0)
#define BULK_G2S(dst, src, bytes, mbar)                                       \
    asm volatile("cp.async.bulk.shared::cluster.global.mbarrier::complete_tx::bytes " \
                 "[%0], [%1], %2, [%3];"                                      \
                 :: "r"((uint32_t)(dst)), "l"(src), "r"((uint32_t)(bytes)),   \
                    "r"((uint32_t)(mbar)) : "memory")

// release+acquire atomic increment on a shared counter
DINL uint32_t atom_inc_acqrel(uint32_t addr) {
    uint32_t old;
    asm volatile("atom.add.acq_rel.cta.shared::cta.u32 %0, [%1], 1;"
                 : "=r"(old) : "r"(addr) : "memory");
    return old;
}

#define LDSM_X4(r, addr)                                                      \
    asm volatile("ldmatrix.sync.aligned.m8n8.x4.shared.b16 {%0,%1,%2,%3}, [%4];" \
        : "=r"((r)[0]), "=r"((r)[1]), "=r"((r)[2]), "=r"((r)[3]) : "r"(addr))

DINL void mma_bf16(float c[4], const uint32_t a[4], uint32_t b0, uint32_t b1) {
    asm volatile(
        "mma.sync.aligned.m16n8k16.row.col.f32.bf16.bf16.f32 "
        "{%0,%1,%2,%3}, {%4,%5,%6,%7}, {%8,%9}, {%0,%1,%2,%3};"
        : "+f"(c[0]), "+f"(c[1]), "+f"(c[2]), "+f"(c[3])
        : "r"(a[0]), "r"(a[1]), "r"(a[2]), "r"(a[3]), "r"(b0), "r"(b1));
}
DINL void mma_f16(float c[4], const uint32_t a[4], uint32_t b0, uint32_t b1) {
    asm volatile(
        "mma.sync.aligned.m16n8k16.row.col.f32.f16.f16.f32 "
        "{%0,%1,%2,%3}, {%4,%5,%6,%7}, {%8,%9}, {%0,%1,%2,%3};"
        : "+f"(c[0]), "+f"(c[1]), "+f"(c[2]), "+f"(c[3])
        : "r"(a[0]), "r"(a[1]), "r"(a[2]), "r"(a[3]), "r"(b0), "r"(b1));
}

// ============================================================================
// Prep kernels: binarize/convert, tile + chunk-swizzle. MLP=2 per thread.
// ============================================================================

// x [8192,4096] f32 -> g_Ax bf16 sign A-tiles (2 chunks per thread)
__global__ void prep_actbf16(const float* __restrict__ x) {
    uint32_t t = blockIdx.x * 256 + threadIdx.x;     // 2,097,152
    uint32_t c2 = t & 3;
    uint32_t r  = (t >> 2) & 127;
    uint32_t ks = (t >> 9) & 63;
    uint32_t mt = t >> 15;
    const float* rowp = x + ((size_t)(mt * 128 + r) * 4096 + ks * 64);
    uint8_t* blk = g_Ax + ((size_t)(mt * 64 + ks) * 128 + r) * 128;
    const float4* s0 = (const float4*)(rowp + c2 * 8);
    const float4* s1 = (const float4*)(rowp + (c2 + 4) * 8);
    float4 f0 = s0[0], f1 = s0[1], f2 = s1[0], f3 = s1[1];
    uint4 o0, o1;
    o0.x = bf16sgn(f0.x) | (bf16sgn(f0.y) << 16);
    o0.y = bf16sgn(f0.z) | (bf16sgn(f0.w) << 16);
    o0.z = bf16sgn(f1.x) | (bf16sgn(f1.y) << 16);
    o0.w = bf16sgn(f1.z) | (bf16sgn(f1.w) << 16);
    o1.x = bf16sgn(f2.x) | (bf16sgn(f2.y) << 16);
    o1.y = bf16sgn(f2.z) | (bf16sgn(f2.w) << 16);
    o1.z = bf16sgn(f3.x) | (bf16sgn(f3.y) << 16);
    o1.w = bf16sgn(f3.z) | (bf16sgn(f3.w) << 16);
    *(uint4*)(blk + ((c2 ^ (r & 7)) << 4))       = o0;
    *(uint4*)(blk + (((c2 + 4) ^ (r & 7)) << 4)) = o1;
}

// w [4096,4096] f32 -> bf16 sign B-tiles (2 chunks per thread)
template <int SEL>
__global__ void prep_wbf16(const float* __restrict__ w) {
    uint32_t t = blockIdx.x * 256 + threadIdx.x;     // 1,048,576
    uint32_t c2 = t & 3;
    uint32_t r  = (t >> 2) & 255;
    uint32_t ks = (t >> 10) & 63;
    uint32_t nt = t >> 16;
    const float* rowp = w + ((size_t)(nt * 256 + r) * 4096 + ks * 64);
    uint8_t* base = (SEL == 0) ? g_W1t : g_W2t;
    uint8_t* blk = base + ((size_t)(nt * 64 + ks) * 256 + r) * 128;
    const float4* s0 = (const float4*)(rowp + c2 * 8);
    const float4* s1 = (const float4*)(rowp + (c2 + 4) * 8);
    float4 f0 = s0[0], f1 = s0[1], f2 = s1[0], f3 = s1[1];
    uint4 o0, o1;
    o0.x = bf16sgn(f0.x) | (bf16sgn(f0.y) << 16);
    o0.y = bf16sgn(f0.z) | (bf16sgn(f0.w) << 16);
    o0.z = bf16sgn(f1.x) | (bf16sgn(f1.y) << 16);
    o0.w = bf16sgn(f1.z) | (bf16sgn(f1.w) << 16);
    o1.x = bf16sgn(f2.x) | (bf16sgn(f2.y) << 16);
    o1.y = bf16sgn(f2.z) | (bf16sgn(f2.w) << 16);
    o1.z = bf16sgn(f3.x) | (bf16sgn(f3.y) << 16);
    o1.w = bf16sgn(f3.z) | (bf16sgn(f3.w) << 16);
    *(uint4*)(blk + ((c2 ^ (r & 7)) << 4))       = o0;
    *(uint4*)(blk + (((c2 + 4) ^ (r & 7)) << 4)) = o1;
}

// w3 [1000,4096] f32 -> fp16 B-tiles (nt*64+ks): 256 rows x 128B, K=4096
__global__ void prep_w3h(const float* __restrict__ w3) {
    uint32_t t = blockIdx.x * 256 + threadIdx.x;     // 524,288
    uint32_t c  = t & 7;
    uint32_t r  = (t >> 3) & 255;
    uint32_t ks = (t >> 11) & 63;
    uint32_t nt = t >> 17;
    int n = (int)(nt * 256 + r);
    float f[8];
    if (n < 1000) {
        const float4* s = (const float4*)(w3 + (size_t)n * 4096 + ks * 64 + c * 8);
        float4 a = s[0], b = s[1];
        f[0] = a.x; f[1] = a.y; f[2] = a.z; f[3] = a.w;
        f[4] = b.x; f[5] = b.y; f[6] = b.z; f[7] = b.w;
    } else {
        #pragma unroll
        for (int i = 0; i < 8; i++) f[i] = 0.0f;
    }
    uint32_t h[8];
    #pragma unroll
    for (int i = 0; i < 8; i++) h[i] = (uint32_t)__half_as_ushort(__float2half(f[i]));
    uint4 o;
    o.x = h[0] | (h[1] << 16); o.y = h[2] | (h[3] << 16);
    o.z = h[4] | (h[5] << 16); o.w = h[6] | (h[7] << 16);
    *(uint4*)(g_B3 + ((size_t)(nt * 64 + ks) * 256 + r) * 128 + ((c ^ (r & 7)) << 4)) = o;
}

// ============================================================================
// Unified 16-bit GEMM: CTA 128x128, 8 warps (2m x 4n), warp tile 64x32.
// Stage = 64 k-elems: A 16KB + B 16KB, 2 slots (64.7KB smem), 2 CTAs/SM.
// Slot recycling: last-finishing warp issues the refill.
// LAYER 1 (bf16): A=g_Ax, B=g_W1t, epi: sign(acc+b) -> g_T1 (bf16 A-tiles)
// LAYER 2 (bf16): A=g_T1, B=g_W2t, epi: sign(acc+b) -> g_T2 (fp16 A-tiles)
// LAYER 3 (fp16): A=g_T2, B=g_B3,  epi: acc+b -> float out [8192,1000]
// ============================================================================
static const int G_STAGE = 32768;                     // 16KB A + 16KB B
static const int G_SMEM  = 2 * G_STAGE + 128 + 512;   // 66176

template <int LAYER>
__global__ void __launch_bounds__(256, 2) gemm_16(const float* __restrict__ bias,
                                                  float* __restrict__ outf) {
    constexpr int KSTG = 64;                          // 64 stages x 64 elems

    extern __shared__ __align__(128) uint8_t smem[];
    const int tid = threadIdx.x, lane = tid & 31, wid = tid >> 5;
    const int mt = blockIdx.x, nt = blockIdx.y;
    const int m_w = (wid >> 2) * 64, n_w = (wid & 3) * 32;
    const uint32_t sbase = smem_u32(smem);
    const uint32_t mfull = sbase + 2 * G_STAGE;        // 2 x 8B mbarriers
    const uint32_t scnt  = mfull + 32;                 // 2 x 4B slot counters
    float* s_bias = (float*)(smem + 2 * G_STAGE + 128);

    const uint8_t* Ablk = (LAYER == 1) ? g_Ax + (size_t)mt * 64 * 16384
                        : (LAYER == 2) ? g_T1 + (size_t)mt * 64 * 16384
                                       : g_T2 + (size_t)mt * 64 * 16384;
    // B: 256-row blocks; this CTA uses 128 rows at n_local within block ntB.
    const uint8_t* Bbase = (LAYER == 1) ? g_W1t : (LAYER == 2) ? g_W2t : g_B3;
    const uint8_t* Bblk = Bbase + ((size_t)(nt >> 1) * 64 * 256 + (size_t)(nt & 1) * 128) * 128;

    if (tid == 0) {
        #pragma unroll
        for (int s = 0; s < 2; s++) {
            MBAR_INIT(mfull + 8 * s, 1);
            *(uint32_t*)(smem + 2 * G_STAGE + 32 + 4 * s) = 0;   // counters
        }
    }
    if (tid < 128) {
        int n = nt * 128 + tid;
        s_bias[tid] = (LAYER == 3) ? ((n < 1000) ? bias[n] : 0.0f) : bias[n];
    }
    __syncthreads();

    auto issue = [&](int ks) {
        const int sl = ks & 1;
        const uint32_t mb = mfull + 8 * sl;
        MBAR_EXPECT_TX(mb, G_STAGE);
        BULK_G2S(sbase + sl * G_STAGE,         Ablk + (size_t)ks * 16384, 16384, mb);
        BULK_G2S(sbase + sl * G_STAGE + 16384, Bblk + (size_t)ks * 32768, 16384, mb);
    };

    float cf[4][4][4];
    #pragma unroll
    for (int a = 0; a < 4; a++)
        #pragma unroll
        for (int b = 0; b < 4; b++)
            #pragma unroll
            for (int q = 0; q < 4; q++) cf[a][b][q] = 0.0f;

    if (tid == 0) { issue(0); issue(1); }

    const uint32_t a_row = (uint32_t)(m_w + ((lane >> 3) & 1) * 8 + (lane & 7));
    const uint32_t a_chi = (uint32_t)(lane >> 4);
    const uint32_t b_row = (uint32_t)(n_w + (lane & 7));
    const uint32_t b_chi = (uint32_t)(lane >> 3);       // 0..3 for x4

    #pragma unroll 1
    for (int ks = 0; ks < KSTG; ks++) {
        const int sl = ks & 1;
        const uint32_t ph = (uint32_t)((ks >> 1) & 1);
        MBAR_WAIT(mfull + 8 * sl, ph);
        const uint32_t sA = sbase + sl * G_STAGE;
        const uint32_t sB = sA + 16384;

        #pragma unroll
        for (int kp = 0; kp < 2; kp++) {            // k-step pairs
            uint32_t b4[4][4];
            #pragma unroll
            for (int ni = 0; ni < 4; ni++) {
                uint32_t rl = b_row + ni * 8;
                uint32_t cc = (uint32_t)(kp * 4) + b_chi;
                LDSM_X4(b4[ni], sB + rl * 128 + (((cc ^ (rl & 7)) << 4)));
            }
            #pragma unroll
            for (int sub = 0; sub < 2; sub++) {
                const int kst = kp * 2 + sub;
                uint32_t a[4][4];
                #pragma unroll
                for (int mi = 0; mi < 4; mi++) {
                    uint32_t rl = a_row + mi * 16;
                    uint32_t cc = (uint32_t)(kst * 2) + a_chi;
                    LDSM_X4(a[mi], sA + rl * 128 + (((cc ^ (rl & 7)) << 4)));
                }
                #pragma unroll
                for (int mi = 0; mi < 4; mi++)
                    #pragma unroll
                    for (int ni = 0; ni < 4; ni++) {
                        if constexpr (LAYER == 3)
                            mma_f16(cf[mi][ni], a[mi], b4[ni][2 * sub], b4[ni][2 * sub + 1]);
                        else
                            mma_bf16(cf[mi][ni], a[mi], b4[ni][2 * sub], b4[ni][2 * sub + 1]);
                    }
            }
        }

        // Slot recycling: last-arriving warp issues the refill (no blocking).
        if (ks + 2 < KSTG && lane == 0) {
            uint32_t old = atom_inc_acqrel(scnt + 4 * sl);
            if ((old & 7u) == 7u) issue(ks + 2);
        }
    }

    // ---------------- epilogue ----------------
    const int g = lane >> 2, t4 = lane & 3;
    #pragma unroll
    for (int mi = 0; mi < 4; mi++) {
        const int rl0 = m_w + mi * 16 + g;               // rows rl0, rl0+8
        #pragma unroll
        for (int ni = 0; ni < 4; ni++) {
            const int nl = n_w + ni * 8 + t4 * 2;        // cols nl, nl+1
            const int ng = nt * 128 + nl;
            const float b0 = s_bias[nl], b1 = s_bias[nl + 1];
            float f0 = cf[mi][ni][0] + b0;
            float f1 = cf[mi][ni][1] + b1;
            float f2 = cf[mi][ni][2] + b0;
            float f3 = cf[mi][ni][3] + b1;
            if constexpr (LAYER == 3) {
                const size_t r0 = (size_t)(mt * 128 + rl0);
                if (ng < 1000) {
                    outf[r0 * 1000 + ng]       = f0;
                    outf[(r0 + 8) * 1000 + ng] = f2;
                }
                if (ng + 1 < 1000) {
                    outf[r0 * 1000 + ng + 1]       = f1;
                    outf[(r0 + 8) * 1000 + ng + 1] = f3;
                }
            } else {
                uint8_t* T = (LAYER == 1) ? g_T1 : g_T2;
                uint32_t p0, p1;
                if constexpr (LAYER == 1) {
                    p0 = bf16sgn(f0) | (bf16sgn(f1) << 16);
                    p1 = bf16sgn(f2) | (bf16sgn(f3) << 16);
                } else {
                    p0 = fp16sgn(f0) | (fp16sgn(f1) << 16);
                    p1 = fp16sgn(f2) | (fp16sgn(f3) << 16);
                }
                const uint32_t nb = (uint32_t)ng * 2;     // byte offset in 8192B row
                const uint32_t ks2 = nb >> 7;
                const uint32_t chk = (nb >> 4) & 7, sub = nb & 15;
                uint8_t* blk = T + (size_t)(mt * 64 + ks2) * 16384;
                uint32_t o0 = (uint32_t)rl0 * 128 + ((chk ^ ((uint32_t)rl0 & 7)) << 4) + sub;
                uint32_t o1 = (uint32_t)(rl0 + 8) * 128 + ((chk ^ ((uint32_t)(rl0 + 8) & 7)) << 4) + sub;
                *(uint32_t*)(blk + o0) = p0;
                *(uint32_t*)(blk + o1) = p1;
            }
        }
    }
}

// ============================================================================
// kernel_launch — launch index 3 (the profiled one) = gemm_16<1>
// ============================================================================
extern "C" void kernel_launch(void* const* d_in, const int* in_sizes, int n_in,
                              void* d_out, int out_size) {
    (void)in_sizes; (void)n_in; (void)out_size;
    const float* x  = (const float*)d_in[0];
    const float* w1 = (const float*)d_in[1];
    const float* b1 = (const float*)d_in[2];
    const float* w2 = (const float*)d_in[3];
    const float* b2 = (const float*)d_in[4];
    const float* w3 = (const float*)d_in[5];
    const float* b3 = (const float*)d_in[6];
    float* out = (float*)d_out;

    cudaFuncSetAttribute(gemm_16<1>, cudaFuncAttributeMaxDynamicSharedMemorySize, G_SMEM);
    cudaFuncSetAttribute(gemm_16<2>, cudaFuncAttributeMaxDynamicSharedMemorySize, G_SMEM);
    cudaFuncSetAttribute(gemm_16<3>, cudaFuncAttributeMaxDynamicSharedMemorySize, G_SMEM);

    prep_actbf16<<<8192, 256>>>(x);                         // 0
    prep_wbf16<0><<<4096, 256>>>(w1);                       // 1
    prep_w3h<<<2048, 256>>>(w3);                            // 2
    gemm_16<1><<<dim3(64, 32), 256, G_SMEM>>>(b1, nullptr); // 3  <- profiled
    prep_wbf16<1><<<4096, 256>>>(w2);                       // 4
    gemm_16<2><<<dim3(64, 32), 256, G_SMEM>>>(b2, nullptr); // 5
    gemm_16<3><<<dim3(64, 8),  256, G_SMEM>>>(b3, out);     // 6
}

// round 16
// speedup vs baseline: 1.0582x; 1.0582x over previous
#include <cuda_runtime.h>
#include <cuda_bf16.h>
#include <cuda_fp16.h>
#include <cstdint>

// ============================================================================
// SimpleBNN on GB300 — sm_103. Round 16 (= round-14 GEMM winner + merged preps).
// MEASURED: bf16/f16 mma.sync m16n8k16 = real tensor HW (~268 TMAC/s achieved,
// 88.5% pipe @ 64x64 warp tiles, 2-slot 96KB bulk pipeline). Probes showed:
// 4-slot 48KB slower (boundary costs), 64x32 tiles slower (L1-bound).
//   L1 (bf16): sign(x) @ sign(w1)^T + b1 -> sign -> bf16 A-tiles
//   L2 (bf16): a1 @ sign(w2)^T + b2      -> sign -> fp16 A-tiles
//   L3 (fp16): a2 @ fp16(w3)^T + b3 -> float out   [K=4096, err 1.8e-4]
// ============================================================================

#define DINL __device__ __forceinline__

// ---------------- device scratch ----------------
// A-tiles: 16KB blocks (mt*64+ks) of 128 rows x 128B (64 elems), chunk c at
//   c ^ (row&7). B-tiles: 32KB blocks (nt*64+ks) of 256 rows x 128B.
__device__ __align__(128) uint8_t g_Ax [(size_t)64 * 64 * 16384];  // sign(x)  bf16 64MB
__device__ __align__(128) uint8_t g_W1t[(size_t)16 * 64 * 32768];  // sign(w1) bf16 32MB
__device__ __align__(128) uint8_t g_W2t[(size_t)16 * 64 * 32768];  // sign(w2) bf16 32MB
__device__ __align__(128) uint8_t g_T1 [(size_t)64 * 64 * 16384];  // a1       bf16 64MB
__device__ __align__(128) uint8_t g_T2 [(size_t)64 * 64 * 16384];  // a2       fp16 64MB
__device__ __align__(128) uint8_t g_B3 [(size_t)4 * 64 * 32768];   // w3       fp16  8MB

// ---------------- helpers ----------------
DINL uint32_t smem_u32(const void* p) {
    uint32_t a;
    asm("{ .reg .u64 t; cvta.to.shared.u64 t, %1; cvt.u32.u64 %0, t; }" : "=r"(a) : "l"(p));
    return a;
}
DINL uint32_t bf16sgn(float v) {    // sign -> bf16 bits (+-1.0 or 0)
    uint32_t u = __float_as_uint(v);
    return ((u << 1) == 0u) ? 0u : (0x3F80u | ((u >> 31) << 15));
}
DINL uint32_t fp16sgn(float v) {    // sign -> fp16 bits (+-1.0 or 0)
    uint32_t u = __float_as_uint(v);
    return ((u << 1) == 0u) ? 0u : (0x3C00u | ((u >> 31) << 15));
}

#define MBAR_INIT(addr, cnt) \
    asm volatile("mbarrier.init.shared.b64 [%0], %1;" :: "r"(addr), "r"(cnt) : "memory")
#define MBAR_EXPECT_TX(addr, tx) \
    asm volatile("mbarrier.arrive.expect_tx.shared.b64 _, [%0], %1;" \
                 :: "r"(addr), "r"(tx) : "memory")
#define MBAR_WAIT(addr, parity) do {                                          \
    asm volatile("{\n\t.reg .pred P1;\n\t"                                    \
        "WAIT_%=:\n\t"                                                        \
        "mbarrier.try_wait.parity.acquire.cta.shared::cta.b64 P1, [%0], %1, 0x989680;\n\t" \
        "@P1 bra.uni DONE_%=;\n\t"                                            \
        "bra.uni WAIT_%=;\n\t"                                                \
        "DONE_%=:\n\t}"                                                       \
        :: "r"((uint32_t)(addr)), "r"((uint32_t)(parity)) : "memory");        \
} while (0)
#define BULK_G2S(dst, src, bytes, mbar)                                       \
    asm volatile("cp.async.bulk.shared::cluster.global.mbarrier::complete_tx::bytes " \
                 "[%0], [%1], %2, [%3];"                                      \
                 :: "r"((uint32_t)(dst)), "l"(src), "r"((uint32_t)(bytes)),   \
                    "r"((uint32_t)(mbar)) : "memory")

// release+acquire atomic increment on a shared counter
DINL uint32_t atom_inc_acqrel(uint32_t addr) {
    uint32_t old;
    asm volatile("atom.add.acq_rel.cta.shared::cta.u32 %0, [%1], 1;"
                 : "=r"(old) : "r"(addr) : "memory");
    return old;
}

#define LDSM_X4(r, addr)                                                      \
    asm volatile("ldmatrix.sync.aligned.m8n8.x4.shared.b16 {%0,%1,%2,%3}, [%4];" \
        : "=r"((r)[0]), "=r"((r)[1]), "=r"((r)[2]), "=r"((r)[3]) : "r"(addr))

DINL void mma_bf16(float c[4], const uint32_t a[4], uint32_t b0, uint32_t b1) {
    asm volatile(
        "mma.sync.aligned.m16n8k16.row.col.f32.bf16.bf16.f32 "
        "{%0,%1,%2,%3}, {%4,%5,%6,%7}, {%8,%9}, {%0,%1,%2,%3};"
        : "+f"(c[0]), "+f"(c[1]), "+f"(c[2]), "+f"(c[3])
        : "r"(a[0]), "r"(a[1]), "r"(a[2]), "r"(a[3]), "r"(b0), "r"(b1));
}
DINL void mma_f16(float c[4], const uint32_t a[4], uint32_t b0, uint32_t b1) {
    asm volatile(
        "mma.sync.aligned.m16n8k16.row.col.f32.f16.f16.f32 "
        "{%0,%1,%2,%3}, {%4,%5,%6,%7}, {%8,%9}, {%0,%1,%2,%3};"
        : "+f"(c[0]), "+f"(c[1]), "+f"(c[2]), "+f"(c[3])
        : "r"(a[0]), "r"(a[1]), "r"(a[2]), "r"(a[3]), "r"(b0), "r"(b1));
}

// ============================================================================
// Prep kernels: binarize/convert, tile + chunk-swizzle. MLP=2 per thread.
// ============================================================================

// x [8192,4096] f32 -> g_Ax bf16 sign A-tiles (2 chunks per thread)
__global__ void prep_actbf16(const float* __restrict__ x) {
    uint32_t t = blockIdx.x * 256 + threadIdx.x;     // 2,097,152
    uint32_t c2 = t & 3;
    uint32_t r  = (t >> 2) & 127;
    uint32_t ks = (t >> 9) & 63;
    uint32_t mt = t >> 15;
    const float* rowp = x + ((size_t)(mt * 128 + r) * 4096 + ks * 64);
    uint8_t* blk = g_Ax + ((size_t)(mt * 64 + ks) * 128 + r) * 128;
    const float4* s0 = (const float4*)(rowp + c2 * 8);
    const float4* s1 = (const float4*)(rowp + (c2 + 4) * 8);
    float4 f0 = s0[0], f1 = s0[1], f2 = s1[0], f3 = s1[1];
    uint4 o0, o1;
    o0.x = bf16sgn(f0.x) | (bf16sgn(f0.y) << 16);
    o0.y = bf16sgn(f0.z) | (bf16sgn(f0.w) << 16);
    o0.z = bf16sgn(f1.x) | (bf16sgn(f1.y) << 16);
    o0.w = bf16sgn(f1.z) | (bf16sgn(f1.w) << 16);
    o1.x = bf16sgn(f2.x) | (bf16sgn(f2.y) << 16);
    o1.y = bf16sgn(f2.z) | (bf16sgn(f2.w) << 16);
    o1.z = bf16sgn(f3.x) | (bf16sgn(f3.y) << 16);
    o1.w = bf16sgn(f3.z) | (bf16sgn(f3.w) << 16);
    *(uint4*)(blk + ((c2 ^ (r & 7)) << 4))       = o0;
    *(uint4*)(blk + (((c2 + 4) ^ (r & 7)) << 4)) = o1;
}

// ALL weight preps in one launch:
//   blocks [0,4096):     w1 -> g_W1t (bf16 sign B-tiles, 2 chunks/thread)
//   blocks [4096,8192):  w2 -> g_W2t (bf16 sign B-tiles, 2 chunks/thread)
//   blocks [8192,10240): w3 -> g_B3  (fp16 B-tiles, 1 chunk/thread)
__global__ void prep_weights(const float* __restrict__ w1,
                             const float* __restrict__ w2,
                             const float* __restrict__ w3) {
    uint32_t b = blockIdx.x;
    if (b < 8192) {
        const float* w = (b < 4096) ? w1 : w2;
        uint8_t* base  = (b < 4096) ? g_W1t : g_W2t;
        uint32_t t = (b & 4095) * 256 + threadIdx.x;   // 1,048,576 per weight
        uint32_t c2 = t & 3;
        uint32_t r  = (t >> 2) & 255;
        uint32_t ks = (t >> 10) & 63;
        uint32_t nt = t >> 16;
        const float* rowp = w + ((size_t)(nt * 256 + r) * 4096 + ks * 64);
        uint8_t* blk = base + ((size_t)(nt * 64 + ks) * 256 + r) * 128;
        const float4* s0 = (const float4*)(rowp + c2 * 8);
        const float4* s1 = (const float4*)(rowp + (c2 + 4) * 8);
        float4 f0 = s0[0], f1 = s0[1], f2 = s1[0], f3 = s1[1];
        uint4 o0, o1;
        o0.x = bf16sgn(f0.x) | (bf16sgn(f0.y) << 16);
        o0.y = bf16sgn(f0.z) | (bf16sgn(f0.w) << 16);
        o0.z = bf16sgn(f1.x) | (bf16sgn(f1.y) << 16);
        o0.w = bf16sgn(f1.z) | (bf16sgn(f1.w) << 16);
        o1.x = bf16sgn(f2.x) | (bf16sgn(f2.y) << 16);
        o1.y = bf16sgn(f2.z) | (bf16sgn(f2.w) << 16);
        o1.z = bf16sgn(f3.x) | (bf16sgn(f3.y) << 16);
        o1.w = bf16sgn(f3.z) | (bf16sgn(f3.w) << 16);
        *(uint4*)(blk + ((c2 ^ (r & 7)) << 4))       = o0;
        *(uint4*)(blk + (((c2 + 4) ^ (r & 7)) << 4)) = o1;
    } else {
        uint32_t t = (b - 8192) * 256 + threadIdx.x;   // 524,288
        uint32_t c  = t & 7;
        uint32_t r  = (t >> 3) & 255;
        uint32_t ks = (t >> 11) & 63;
        uint32_t nt = t >> 17;
        int n = (int)(nt * 256 + r);
        float f[8];
        if (n < 1000) {
            const float4* s = (const float4*)(w3 + (size_t)n * 4096 + ks * 64 + c * 8);
            float4 a = s[0], bb = s[1];
            f[0] = a.x; f[1] = a.y; f[2] = a.z; f[3] = a.w;
            f[4] = bb.x; f[5] = bb.y; f[6] = bb.z; f[7] = bb.w;
        } else {
            #pragma unroll
            for (int i = 0; i < 8; i++) f[i] = 0.0f;
        }
        uint32_t h[8];
        #pragma unroll
        for (int i = 0; i < 8; i++) h[i] = (uint32_t)__half_as_ushort(__float2half(f[i]));
        uint4 o;
        o.x = h[0] | (h[1] << 16); o.y = h[2] | (h[3] << 16);
        o.z = h[4] | (h[5] << 16); o.w = h[6] | (h[7] << 16);
        *(uint4*)(g_B3 + ((size_t)(nt * 64 + ks) * 256 + r) * 128 + ((c ^ (r & 7)) << 4)) = o;
    }
}

// ============================================================================
// Unified 16-bit GEMM (round-14 winner): CTA 128x256, 8 warps (2m x 4n),
// warp tile 64x64. Stage = 128 k-elems: A 32KB + B 64KB, one bulk copy each,
// 2 slots (192KB). Slot recycling: last-finishing warp issues refill.
// LAYER 1 (bf16): A=g_Ax, B=g_W1t, epi: sign(acc+b) -> g_T1 (bf16 A-tiles)
// LAYER 2 (bf16): A=g_T1, B=g_W2t, epi: sign(acc+b) -> g_T2 (fp16 A-tiles)
// LAYER 3 (fp16): A=g_T2, B=g_B3,  epi: acc+b -> float out [8192,1000]
// ============================================================================
static const int G_STAGE = 98304;                     // 32KB A + 64KB B
static const int G_SMEM  = 2 * G_STAGE + 128 + 1024;  // 197760

template <int LAYER>
__global__ void __launch_bounds__(256, 1) gemm_16(const float* __restrict__ bias,
                                                  float* __restrict__ outf) {
    constexpr int KSTG = 32;                          // 32 stages x 128 elems

    extern __shared__ __align__(128) uint8_t smem[];
    const int tid = threadIdx.x, lane = tid & 31, wid = tid >> 5;
    const int mt = blockIdx.x, nt = blockIdx.y;
    const int m_w = (wid >> 2) * 64, n_w = (wid & 3) * 64;
    const uint32_t sbase = smem_u32(smem);
    const uint32_t mfull = sbase + 2 * G_STAGE;        // 2 x 8B mbarriers
    const uint32_t scnt  = mfull + 32;                 // 2 x 4B slot counters
    float* s_bias = (float*)(smem + 2 * G_STAGE + 128);

    const uint8_t* Ablk = (LAYER == 1) ? g_Ax + (size_t)mt * 64 * 16384
                        : (LAYER == 2) ? g_T1 + (size_t)mt * 64 * 16384
                                       : g_T2 + (size_t)mt * 64 * 16384;
    const uint8_t* Bblk = (LAYER == 1) ? g_W1t + (size_t)nt * 64 * 32768
                        : (LAYER == 2) ? g_W2t + (size_t)nt * 64 * 32768
                                       : g_B3  + (size_t)nt * 64 * 32768;

    if (tid == 0) {
        #pragma unroll
        for (int s = 0; s < 2; s++) {
            MBAR_INIT(mfull + 8 * s, 1);
            *(uint32_t*)(smem + 2 * G_STAGE + 32 + 4 * s) = 0;   // counters
        }
    }
    {
        int n = nt * 256 + tid;
        s_bias[tid] = (LAYER == 3) ? ((n < 1000) ? bias[n] : 0.0f) : bias[n];
    }
    __syncthreads();

    auto issue = [&](int ks) {
        const int sl = ks & 1;
        const uint32_t mb = mfull + 8 * sl;
        MBAR_EXPECT_TX(mb, G_STAGE);
        BULK_G2S(sbase + sl * G_STAGE,         Ablk + (size_t)ks * 32768,  32768, mb);
        BULK_G2S(sbase + sl * G_STAGE + 32768, Bblk + (size_t)ks * 65536,  65536, mb);
    };

    float cf[4][8][4];
    #pragma unroll
    for (int a = 0; a < 4; a++)
        #pragma unroll
        for (int b = 0; b < 8; b++)
            #pragma unroll
            for (int q = 0; q < 4; q++) cf[a][b][q] = 0.0f;

    if (tid == 0) { issue(0); issue(1); }

    const uint32_t a_row = (uint32_t)(m_w + ((lane >> 3) & 1) * 8 + (lane & 7));
    const uint32_t a_chi = (uint32_t)(lane >> 4);
    const uint32_t b_row = (uint32_t)(n_w + (lane & 7));
    const uint32_t b_chi = (uint32_t)(lane >> 3);       // 0..3 for x4

    #pragma unroll 1
    for (int ks = 0; ks < KSTG; ks++) {
        const int sl = ks & 1;
        const uint32_t ph = (uint32_t)((ks >> 1) & 1);
        MBAR_WAIT(mfull + 8 * sl, ph);
        const uint32_t sA = sbase + sl * G_STAGE;       // 2 A blocks
        const uint32_t sB = sA + 32768;                 // 2 B blocks

        #pragma unroll
        for (int kb = 0; kb < 2; kb++) {                // 16KB/32KB block pair
            const uint32_t uA = sA + (uint32_t)kb * 16384;
            const uint32_t uB = sB + (uint32_t)kb * 32768;
            #pragma unroll
            for (int kp = 0; kp < 2; kp++) {            // k-step pairs
                uint32_t b4[8][4];
                #pragma unroll
                for (int ni = 0; ni < 8; ni++) {
                    uint32_t rl = b_row + ni * 8;
                    uint32_t cc = (uint32_t)(kp * 4) + b_chi;
                    LDSM_X4(b4[ni], uB + rl * 128 + (((cc ^ (rl & 7)) << 4)));
                }
                #pragma unroll
                for (int sub = 0; sub < 2; sub++) {
                    const int kst = kp * 2 + sub;
                    uint32_t a[4][4];
                    #pragma unroll
                    for (int mi = 0; mi < 4; mi++) {
                        uint32_t rl = a_row + mi * 16;
                        uint32_t cc = (uint32_t)(kst * 2) + a_chi;
                        LDSM_X4(a[mi], uA + rl * 128 + (((cc ^ (rl & 7)) << 4)));
                    }
                    #pragma unroll
                    for (int mi = 0; mi < 4; mi++)
                        #pragma unroll
                        for (int ni = 0; ni < 8; ni++) {
                            if constexpr (LAYER == 3)
                                mma_f16(cf[mi][ni], a[mi], b4[ni][2 * sub], b4[ni][2 * sub + 1]);
                            else
                                mma_bf16(cf[mi][ni], a[mi], b4[ni][2 * sub], b4[ni][2 * sub + 1]);
                        }
                }
            }
        }

        // Slot recycling: last-arriving warp issues the refill (no blocking).
        if (ks + 2 < KSTG && lane == 0) {
            uint32_t old = atom_inc_acqrel(scnt + 4 * sl);
            if ((old & 7u) == 7u) issue(ks + 2);
        }
    }

    // ---------------- epilogue ----------------
    const int g = lane >> 2, t4 = lane & 3;
    #pragma unroll
    for (int mi = 0; mi < 4; mi++) {
        const int rl0 = m_w + mi * 16 + g;               // rows rl0, rl0+8
        #pragma unroll
        for (int ni = 0; ni < 8; ni++) {
            const int nl = n_w + ni * 8 + t4 * 2;        // cols nl, nl+1
            const int ng = nt * 256 + nl;
            const float b0 = s_bias[nl], b1 = s_bias[nl + 1];
            float f0 = cf[mi][ni][0] + b0;
            float f1 = cf[mi][ni][1] + b1;
            float f2 = cf[mi][ni][2] + b0;
            float f3 = cf[mi][ni][3] + b1;
            if constexpr (LAYER == 3) {
                const size_t r0 = (size_t)(mt * 128 + rl0);
                if (ng < 1000) {
                    outf[r0 * 1000 + ng]       = f0;
                    outf[(r0 + 8) * 1000 + ng] = f2;
                }
                if (ng + 1 < 1000) {
                    outf[r0 * 1000 + ng + 1]       = f1;
                    outf[(r0 + 8) * 1000 + ng + 1] = f3;
                }
            } else {
                uint8_t* T = (LAYER == 1) ? g_T1 : g_T2;
                uint32_t p0, p1;
                if constexpr (LAYER == 1) {
                    p0 = bf16sgn(f0) | (bf16sgn(f1) << 16);
                    p1 = bf16sgn(f2) | (bf16sgn(f3) << 16);
                } else {
                    p0 = fp16sgn(f0) | (fp16sgn(f1) << 16);
                    p1 = fp16sgn(f2) | (fp16sgn(f3) << 16);
                }
                const uint32_t nb = (uint32_t)ng * 2;     // byte offset in 8192B row
                const uint32_t ks2 = nb >> 7;
                const uint32_t chk = (nb >> 4) & 7, sub = nb & 15;
                uint8_t* blk = T + (size_t)(mt * 64 + ks2) * 16384;
                uint32_t o0 = (uint32_t)rl0 * 128 + ((chk ^ ((uint32_t)rl0 & 7)) << 4) + sub;
                uint32_t o1 = (uint32_t)(rl0 + 8) * 128 + ((chk ^ ((uint32_t)(rl0 + 8) & 7)) << 4) + sub;
                *(uint32_t*)(blk + o0) = p0;
                *(uint32_t*)(blk + o1) = p1;
            }
        }
    }
}

// ============================================================================
// kernel_launch
// ============================================================================
extern "C" void kernel_launch(void* const* d_in, const int* in_sizes, int n_in,
                              void* d_out, int out_size) {
    (void)in_sizes; (void)n_in; (void)out_size;
    const float* x  = (const float*)d_in[0];
    const float* w1 = (const float*)d_in[1];
    const float* b1 = (const float*)d_in[2];
    const float* w2 = (const float*)d_in[3];
    const float* b2 = (const float*)d_in[4];
    const float* w3 = (const float*)d_in[5];
    const float* b3 = (const float*)d_in[6];
    float* out = (float*)d_out;

    cudaFuncSetAttribute(gemm_16<1>, cudaFuncAttributeMaxDynamicSharedMemorySize, G_SMEM);
    cudaFuncSetAttribute(gemm_16<2>, cudaFuncAttributeMaxDynamicSharedMemorySize, G_SMEM);
    cudaFuncSetAttribute(gemm_16<3>, cudaFuncAttributeMaxDynamicSharedMemorySize, G_SMEM);

    prep_actbf16<<<8192, 256>>>(x);                         // 0
    prep_weights<<<10240, 256>>>(w1, w2, w3);               // 1
    gemm_16<1><<<dim3(64, 16), 256, G_SMEM>>>(b1, nullptr); // 2
    gemm_16<2><<<dim3(64, 16), 256, G_SMEM>>>(b2, nullptr); // 3  <- profiled
    gemm_16<3><<<dim3(64, 4),  256, G_SMEM>>>(b3, out);     // 4
}

// round 17
// speedup vs baseline: 1.0592x; 1.0009x over previous
#include <cuda_runtime.h>
#include <cuda_bf16.h>
#include <cuda_fp16.h>
#include <cstdint>

// ============================================================================
// SimpleBNN on GB300 — sm_103. Round 17 (= round-16 + A-fragment prefetch).
// MEASURED: bf16/f16 mma.sync m16n8k16 real tensor HW, 88.5% pipe @ 64x64
// warp tiles, 2-slot 96KB bulk pipeline (4-slot slower; 64x32 L1-bound).
//   L1 (bf16): sign(x) @ sign(w1)^T + b1 -> sign -> bf16 A-tiles
//   L2 (bf16): a1 @ sign(w2)^T + b2      -> sign -> fp16 A-tiles
//   L3 (fp16): a2 @ fp16(w3)^T + b3 -> float out   [K=4096, err 1.8e-4]
// Round 17: stage flattened to 8 k-steps with double-buffered A fragments
// (prefetch kst+1 during kst's MMAs); next pair's B issued post-odd-kst.
// ============================================================================

#define DINL __device__ __forceinline__

// ---------------- device scratch ----------------
__device__ __align__(128) uint8_t g_Ax [(size_t)64 * 64 * 16384];  // sign(x)  bf16 64MB
__device__ __align__(128) uint8_t g_W1t[(size_t)16 * 64 * 32768];  // sign(w1) bf16 32MB
__device__ __align__(128) uint8_t g_W2t[(size_t)16 * 64 * 32768];  // sign(w2) bf16 32MB
__device__ __align__(128) uint8_t g_T1 [(size_t)64 * 64 * 16384];  // a1       bf16 64MB
__device__ __align__(128) uint8_t g_T2 [(size_t)64 * 64 * 16384];  // a2       fp16 64MB
__device__ __align__(128) uint8_t g_B3 [(size_t)4 * 64 * 32768];   // w3       fp16  8MB

// ---------------- helpers ----------------
DINL uint32_t smem_u32(const void* p) {
    uint32_t a;
    asm("{ .reg .u64 t; cvta.to.shared.u64 t, %1; cvt.u32.u64 %0, t; }" : "=r"(a) : "l"(p));
    return a;
}
DINL uint32_t bf16sgn(float v) {    // sign -> bf16 bits (+-1.0 or 0)
    uint32_t u = __float_as_uint(v);
    return ((u << 1) == 0u) ? 0u : (0x3F80u | ((u >> 31) << 15));
}
DINL uint32_t fp16sgn(float v) {    // sign -> fp16 bits (+-1.0 or 0)
    uint32_t u = __float_as_uint(v);
    return ((u << 1) == 0u) ? 0u : (0x3C00u | ((u >> 31) << 15));
}

#define MBAR_INIT(addr, cnt) \
    asm volatile("mbarrier.init.shared.b64 [%0], %1;" :: "r"(addr), "r"(cnt) : "memory")
#define MBAR_EXPECT_TX(addr, tx) \
    asm volatile("mbarrier.arrive.expect_tx.shared.b64 _, [%0], %1;" \
                 :: "r"(addr), "r"(tx) : "memory")
#define MBAR_WAIT(addr, parity) do {                                          \
    asm volatile("{\n\t.reg .pred P1;\n\t"                                    \
        "WAIT_%=:\n\t"                                                        \
        "mbarrier.try_wait.parity.acquire.cta.shared::cta.b64 P1, [%0], %1, 0x989680;\n\t" \
        "@P1 bra.uni DONE_%=;\n\t"                                            \
        "bra.uni WAIT_%=;\n\t"                                                \
        "DONE_%=:\n\t}"                                                       \
        :: "r"((uint32_t)(addr)), "r"((uint32_t)(parity)) : "memory");        \
} while (0)
#define BULK_G2S(dst, src, bytes, mbar)                                       \
    asm volatile("cp.async.bulk.shared::cluster.global.mbarrier::complete_tx::bytes " \
                 "[%0], [%1], %2, [%3];"                                      \
                 :: "r"((uint32_t)(dst)), "l"(src), "r"((uint32_t)(bytes)),   \
                    "r"((uint32_t)(mbar)) : "memory")

// release+acquire atomic increment on a shared counter
DINL uint32_t atom_inc_acqrel(uint32_t addr) {
    uint32_t old;
    asm volatile("atom.add.acq_rel.cta.shared::cta.u32 %0, [%1], 1;"
                 : "=r"(old) : "r"(addr) : "memory");
    return old;
}

#define LDSM_X4(r, addr)                                                      \
    asm volatile("ldmatrix.sync.aligned.m8n8.x4.shared.b16 {%0,%1,%2,%3}, [%4];" \
        : "=r"((r)[0]), "=r"((r)[1]), "=r"((r)[2]), "=r"((r)[3]) : "r"(addr))

DINL void mma_bf16(float c[4], const uint32_t a[4], uint32_t b0, uint32_t b1) {
    asm volatile(
        "mma.sync.aligned.m16n8k16.row.col.f32.bf16.bf16.f32 "
        "{%0,%1,%2,%3}, {%4,%5,%6,%7}, {%8,%9}, {%0,%1,%2,%3};"
        : "+f"(c[0]), "+f"(c[1]), "+f"(c[2]), "+f"(c[3])
        : "r"(a[0]), "r"(a[1]), "r"(a[2]), "r"(a[3]), "r"(b0), "r"(b1));
}
DINL void mma_f16(float c[4], const uint32_t a[4], uint32_t b0, uint32_t b1) {
    asm volatile(
        "mma.sync.aligned.m16n8k16.row.col.f32.f16.f16.f32 "
        "{%0,%1,%2,%3}, {%4,%5,%6,%7}, {%8,%9}, {%0,%1,%2,%3};"
        : "+f"(c[0]), "+f"(c[1]), "+f"(c[2]), "+f"(c[3])
        : "r"(a[0]), "r"(a[1]), "r"(a[2]), "r"(a[3]), "r"(b0), "r"(b1));
}

// ============================================================================
// Prep kernels: binarize/convert, tile + chunk-swizzle. MLP=2 per thread.
// ============================================================================

// x [8192,4096] f32 -> g_Ax bf16 sign A-tiles (2 chunks per thread)
__global__ void prep_actbf16(const float* __restrict__ x) {
    uint32_t t = blockIdx.x * 256 + threadIdx.x;     // 2,097,152
    uint32_t c2 = t & 3;
    uint32_t r  = (t >> 2) & 127;
    uint32_t ks = (t >> 9) & 63;
    uint32_t mt = t >> 15;
    const float* rowp = x + ((size_t)(mt * 128 + r) * 4096 + ks * 64);
    uint8_t* blk = g_Ax + ((size_t)(mt * 64 + ks) * 128 + r) * 128;
    const float4* s0 = (const float4*)(rowp + c2 * 8);
    const float4* s1 = (const float4*)(rowp + (c2 + 4) * 8);
    float4 f0 = s0[0], f1 = s0[1], f2 = s1[0], f3 = s1[1];
    uint4 o0, o1;
    o0.x = bf16sgn(f0.x) | (bf16sgn(f0.y) << 16);
    o0.y = bf16sgn(f0.z) | (bf16sgn(f0.w) << 16);
    o0.z = bf16sgn(f1.x) | (bf16sgn(f1.y) << 16);
    o0.w = bf16sgn(f1.z) | (bf16sgn(f1.w) << 16);
    o1.x = bf16sgn(f2.x) | (bf16sgn(f2.y) << 16);
    o1.y = bf16sgn(f2.z) | (bf16sgn(f2.w) << 16);
    o1.z = bf16sgn(f3.x) | (bf16sgn(f3.y) << 16);
    o1.w = bf16sgn(f3.z) | (bf16sgn(f3.w) << 16);
    *(uint4*)(blk + ((c2 ^ (r & 7)) << 4))       = o0;
    *(uint4*)(blk + (((c2 + 4) ^ (r & 7)) << 4)) = o1;
}

// ALL weight preps in one launch:
//   blocks [0,4096):     w1 -> g_W1t ; [4096,8192): w2 -> g_W2t ;
//   blocks [8192,10240): w3 -> g_B3 (fp16)
__global__ void prep_weights(const float* __restrict__ w1,
                             const float* __restrict__ w2,
                             const float* __restrict__ w3) {
    uint32_t b = blockIdx.x;
    if (b < 8192) {
        const float* w = (b < 4096) ? w1 : w2;
        uint8_t* base  = (b < 4096) ? g_W1t : g_W2t;
        uint32_t t = (b & 4095) * 256 + threadIdx.x;
        uint32_t c2 = t & 3;
        uint32_t r  = (t >> 2) & 255;
        uint32_t ks = (t >> 10) & 63;
        uint32_t nt = t >> 16;
        const float* rowp = w + ((size_t)(nt * 256 + r) * 4096 + ks * 64);
        uint8_t* blk = base + ((size_t)(nt * 64 + ks) * 256 + r) * 128;
        const float4* s0 = (const float4*)(rowp + c2 * 8);
        const float4* s1 = (const float4*)(rowp + (c2 + 4) * 8);
        float4 f0 = s0[0], f1 = s0[1], f2 = s1[0], f3 = s1[1];
        uint4 o0, o1;
        o0.x = bf16sgn(f0.x) | (bf16sgn(f0.y) << 16);
        o0.y = bf16sgn(f0.z) | (bf16sgn(f0.w) << 16);
        o0.z = bf16sgn(f1.x) | (bf16sgn(f1.y) << 16);
        o0.w = bf16sgn(f1.z) | (bf16sgn(f1.w) << 16);
        o1.x = bf16sgn(f2.x) | (bf16sgn(f2.y) << 16);
        o1.y = bf16sgn(f2.z) | (bf16sgn(f2.w) << 16);
        o1.z = bf16sgn(f3.x) | (bf16sgn(f3.y) << 16);
        o1.w = bf16sgn(f3.z) | (bf16sgn(f3.w) << 16);
        *(uint4*)(blk + ((c2 ^ (r & 7)) << 4))       = o0;
        *(uint4*)(blk + (((c2 + 4) ^ (r & 7)) << 4)) = o1;
    } else {
        uint32_t t = (b - 8192) * 256 + threadIdx.x;
        uint32_t c  = t & 7;
        uint32_t r  = (t >> 3) & 255;
        uint32_t ks = (t >> 11) & 63;
        uint32_t nt = t >> 17;
        int n = (int)(nt * 256 + r);
        float f[8];
        if (n < 1000) {
            const float4* s = (const float4*)(w3 + (size_t)n * 4096 + ks * 64 + c * 8);
            float4 a = s[0], bb = s[1];
            f[0] = a.x; f[1] = a.y; f[2] = a.z; f[3] = a.w;
            f[4] = bb.x; f[5] = bb.y; f[6] = bb.z; f[7] = bb.w;
        } else {
            #pragma unroll
            for (int i = 0; i < 8; i++) f[i] = 0.0f;
        }
        uint32_t h[8];
        #pragma unroll
        for (int i = 0; i < 8; i++) h[i] = (uint32_t)__half_as_ushort(__float2half(f[i]));
        uint4 o;
        o.x = h[0] | (h[1] << 16); o.y = h[2] | (h[3] << 16);
        o.z = h[4] | (h[5] << 16); o.w = h[6] | (h[7] << 16);
        *(uint4*)(g_B3 + ((size_t)(nt * 64 + ks) * 256 + r) * 128 + ((c ^ (r & 7)) << 4)) = o;
    }
}

// ============================================================================
// Unified 16-bit GEMM: CTA 128x256, 8 warps (2m x 4n), warp tile 64x64.
// Stage = 128 k-elems: A 32KB + B 64KB, 2 slots (192KB). Stage body is a
// flat 8-kstep loop with double-buffered A fragments (prefetch depth 1).
// LAYER 1 (bf16): A=g_Ax, B=g_W1t, epi: sign(acc+b) -> g_T1 (bf16 A-tiles)
// LAYER 2 (bf16): A=g_T1, B=g_W2t, epi: sign(acc+b) -> g_T2 (fp16 A-tiles)
// LAYER 3 (fp16): A=g_T2, B=g_B3,  epi: acc+b -> float out [8192,1000]
// ============================================================================
static const int G_STAGE = 98304;                     // 32KB A + 64KB B
static const int G_SMEM  = 2 * G_STAGE + 128 + 1024;  // 197760

template <int LAYER>
__global__ void __launch_bounds__(256, 1) gemm_16(const float* __restrict__ bias,
                                                  float* __restrict__ outf) {
    constexpr int KSTG = 32;                          // 32 stages x 128 elems

    extern __shared__ __align__(128) uint8_t smem[];
    const int tid = threadIdx.x, lane = tid & 31, wid = tid >> 5;
    const int mt = blockIdx.x, nt = blockIdx.y;
    const int m_w = (wid >> 2) * 64, n_w = (wid & 3) * 64;
    const uint32_t sbase = smem_u32(smem);
    const uint32_t mfull = sbase + 2 * G_STAGE;        // 2 x 8B mbarriers
    const uint32_t scnt  = mfull + 32;                 // 2 x 4B slot counters
    float* s_bias = (float*)(smem + 2 * G_STAGE + 128);

    const uint8_t* Ablk = (LAYER == 1) ? g_Ax + (size_t)mt * 64 * 16384
                        : (LAYER == 2) ? g_T1 + (size_t)mt * 64 * 16384
                                       : g_T2 + (size_t)mt * 64 * 16384;
    const uint8_t* Bblk = (LAYER == 1) ? g_W1t + (size_t)nt * 64 * 32768
                        : (LAYER == 2) ? g_W2t + (size_t)nt * 64 * 32768
                                       : g_B3  + (size_t)nt * 64 * 32768;

    if (tid == 0) {
        #pragma unroll
        for (int s = 0; s < 2; s++) {
            MBAR_INIT(mfull + 8 * s, 1);
            *(uint32_t*)(smem + 2 * G_STAGE + 32 + 4 * s) = 0;   // counters
        }
    }
    {
        int n = nt * 256 + tid;
        s_bias[tid] = (LAYER == 3) ? ((n < 1000) ? bias[n] : 0.0f) : bias[n];
    }
    __syncthreads();

    auto issue = [&](int ks) {
        const int sl = ks & 1;
        const uint32_t mb = mfull + 8 * sl;
        MBAR_EXPECT_TX(mb, G_STAGE);
        BULK_G2S(sbase + sl * G_STAGE,         Ablk + (size_t)ks * 32768,  32768, mb);
        BULK_G2S(sbase + sl * G_STAGE + 32768, Bblk + (size_t)ks * 65536,  65536, mb);
    };

    float cf[4][8][4];
    #pragma unroll
    for (int a = 0; a < 4; a++)
        #pragma unroll
        for (int b = 0; b < 8; b++)
            #pragma unroll
            for (int q = 0; q < 4; q++) cf[a][b][q] = 0.0f;

    if (tid == 0) { issue(0); issue(1); }

    const uint32_t a_row = (uint32_t)(m_w + ((lane >> 3) & 1) * 8 + (lane & 7));
    const uint32_t a_chi = (uint32_t)(lane >> 4);
    const uint32_t b_row = (uint32_t)(n_w + (lane & 7));
    const uint32_t b_chi = (uint32_t)(lane >> 3);       // 0..3 for x4

    #pragma unroll 1
    for (int ks = 0; ks < KSTG; ks++) {
        const int sl = ks & 1;
        const uint32_t ph = (uint32_t)((ks >> 1) & 1);
        MBAR_WAIT(mfull + 8 * sl, ph);
        const uint32_t sA = sbase + sl * G_STAGE;       // 2 A blocks
        const uint32_t sB = sA + 32768;                 // 2 B blocks

        // Flat 8 k-steps, A fragments double-buffered (prefetch depth 1).
        uint32_t abuf[2][4][4];
        uint32_t b4[8][4];

        // kst g: A block = g>>2, chunk = (g&3)*2 + a_chi
        // pair p = g>>1: B block = p>>1, chunk = (p&1)*4 + b_chi
        auto loadA = [&](int g, uint32_t (&dst)[4][4]) {
            const uint32_t uA = sA + (uint32_t)(g >> 2) * 16384;
            const uint32_t cc = (uint32_t)((g & 3) * 2) + a_chi;
            #pragma unroll
            for (int mi = 0; mi < 4; mi++) {
                uint32_t rl = a_row + mi * 16;
                LDSM_X4(dst[mi], uA + rl * 128 + (((cc ^ (rl & 7)) << 4)));
            }
        };
        auto loadB = [&](int p) {
            const uint32_t uB = sB + (uint32_t)(p >> 1) * 32768;
            const uint32_t cc = (uint32_t)((p & 1) * 4) + b_chi;
            #pragma unroll
            for (int ni = 0; ni < 8; ni++) {
                uint32_t rl = b_row + ni * 8;
                LDSM_X4(b4[ni], uB + rl * 128 + (((cc ^ (rl & 7)) << 4)));
            }
        };

        loadB(0);
        loadA(0, abuf[0]);
        #pragma unroll
        for (int g = 0; g < 8; g++) {
            if (g < 7) loadA(g + 1, abuf[(g + 1) & 1]);   // prefetch next A
            const int sub = g & 1;
            #pragma unroll
            for (int mi = 0; mi < 4; mi++)
                #pragma unroll
                for (int ni = 0; ni < 8; ni++) {
                    if constexpr (LAYER == 3)
                        mma_f16(cf[mi][ni], abuf[g & 1][mi], b4[ni][2 * sub], b4[ni][2 * sub + 1]);
                    else
                        mma_bf16(cf[mi][ni], abuf[g & 1][mi], b4[ni][2 * sub], b4[ni][2 * sub + 1]);
                }
            if (sub == 1 && g < 7) loadB((g + 1) >> 1);   // next pair's B
        }

        // Slot recycling: last-arriving warp issues the refill (no blocking).
        if (ks + 2 < KSTG && lane == 0) {
            uint32_t old = atom_inc_acqrel(scnt + 4 * sl);
            if ((old & 7u) == 7u) issue(ks + 2);
        }
    }

    // ---------------- epilogue ----------------
    const int g = lane >> 2, t4 = lane & 3;
    #pragma unroll
    for (int mi = 0; mi < 4; mi++) {
        const int rl0 = m_w + mi * 16 + g;               // rows rl0, rl0+8
        #pragma unroll
        for (int ni = 0; ni < 8; ni++) {
            const int nl = n_w + ni * 8 + t4 * 2;        // cols nl, nl+1
            const int ng = nt * 256 + nl;
            const float b0 = s_bias[nl], b1 = s_bias[nl + 1];
            float f0 = cf[mi][ni][0] + b0;
            float f1 = cf[mi][ni][1] + b1;
            float f2 = cf[mi][ni][2] + b0;
            float f3 = cf[mi][ni][3] + b1;
            if constexpr (LAYER == 3) {
                const size_t r0 = (size_t)(mt * 128 + rl0);
                if (ng < 1000) {
                    outf[r0 * 1000 + ng]       = f0;
                    outf[(r0 + 8) * 1000 + ng] = f2;
                }
                if (ng + 1 < 1000) {
                    outf[r0 * 1000 + ng + 1]       = f1;
                    outf[(r0 + 8) * 1000 + ng + 1] = f3;
                }
            } else {
                uint8_t* T = (LAYER == 1) ? g_T1 : g_T2;
                uint32_t p0, p1;
                if constexpr (LAYER == 1) {
                    p0 = bf16sgn(f0) | (bf16sgn(f1) << 16);
                    p1 = bf16sgn(f2) | (bf16sgn(f3) << 16);
                } else {
                    p0 = fp16sgn(f0) | (fp16sgn(f1) << 16);
                    p1 = fp16sgn(f2) | (fp16sgn(f3) << 16);
                }
                const uint32_t nb = (uint32_t)ng * 2;     // byte offset in 8192B row
                const uint32_t ks2 = nb >> 7;
                const uint32_t chk = (nb >> 4) & 7, sub = nb & 15;
                uint8_t* blk = T + (size_t)(mt * 64 + ks2) * 16384;
                uint32_t o0 = (uint32_t)rl0 * 128 + ((chk ^ ((uint32_t)rl0 & 7)) << 4) + sub;
                uint32_t o1 = (uint32_t)(rl0 + 8) * 128 + ((chk ^ ((uint32_t)(rl0 + 8) & 7)) << 4) + sub;
                *(uint32_t*)(blk + o0) = p0;
                *(uint32_t*)(blk + o1) = p1;
            }
        }
    }
}

// ============================================================================
// kernel_launch
// ============================================================================
extern "C" void kernel_launch(void* const* d_in, const int* in_sizes, int n_in,
                              void* d_out, int out_size) {
    (void)in_sizes; (void)n_in; (void)out_size;
    const float* x  = (const float*)d_in[0];
    const float* w1 = (const float*)d_in[1];
    const float* b1 = (const float*)d_in[2];
    const float* w2 = (const float*)d_in[3];
    const float* b2 = (const float*)d_in[4];
    const float* w3 = (const float*)d_in[5];
    const float* b3 = (const float*)d_in[6];
    float* out = (float*)d_out;

    cudaFuncSetAttribute(gemm_16<1>, cudaFuncAttributeMaxDynamicSharedMemorySize, G_SMEM);
    cudaFuncSetAttribute(gemm_16<2>, cudaFuncAttributeMaxDynamicSharedMemorySize, G_SMEM);
    cudaFuncSetAttribute(gemm_16<3>, cudaFuncAttributeMaxDynamicSharedMemorySize, G_SMEM);

    prep_actbf16<<<8192, 256>>>(x);                         // 0
    prep_weights<<<10240, 256>>>(w1, w2, w3);               // 1
    gemm_16<1><<<dim3(64, 16), 256, G_SMEM>>>(b1, nullptr); // 2
    gemm_16<2><<<dim3(64, 16), 256, G_SMEM>>>(b2, nullptr); // 3  <- profiled
    gemm_16<3><<<dim3(64, 4),  256, G_SMEM>>>(b3, out);     // 4
}